// round 9
// baseline (speedup 1.0000x reference)
#include <cuda_runtime.h>
#include <cstdint>

// NATTEN 7x7, B=2, heads=8, d=32, 56x56, fp32.
// x: (B,768,56,56) qkv-packed; rpb: (8,13,13); out: (B,256,56,56).
// 448 threads/CTA = 448 queries (8 rows x 56 cols), one FULL-d query per
// thread: no shuffles, no masking, maximal ILP. Batch softmax without
// max-shift (logits are O(5), fp32-safe).

#define HH 56
#define WW 56
#define PLANE 3136
#define ROWS 8
#define SROWS 14
#define NT 448
#define CS 36                 // col stride (floats)
#define RSTRIDE 2020          // row stride (floats), 2020 mod 8 == 4
#define TELEMS (SROWS * RSTRIDE)   // 28280 floats per tensor

__device__ __forceinline__ uint64_t pack2(float lo, float hi) {
    uint64_t r; asm("mov.b64 %0, {%1,%2};" : "=l"(r) : "f"(lo), "f"(hi)); return r;
}
__device__ __forceinline__ float2 unpack2(uint64_t v) {
    float2 f; asm("mov.b64 {%0,%1}, %2;" : "=f"(f.x), "=f"(f.y) : "l"(v)); return f;
}
__device__ __forceinline__ uint64_t ffma2(uint64_t a, uint64_t b, uint64_t c) {
    uint64_t d; asm("fma.rn.f32x2 %0, %1, %2, %3;" : "=l"(d) : "l"(a), "l"(b), "l"(c)); return d;
}
__device__ __forceinline__ uint64_t fadd2(uint64_t a, uint64_t b) {
    uint64_t d; asm("add.rn.f32x2 %0, %1, %2;" : "=l"(d) : "l"(a), "l"(b)); return d;
}
__device__ __forceinline__ void lds16(uint32_t a, uint64_t& x, uint64_t& y) {
    asm volatile("ld.shared.v2.b64 {%0,%1}, [%2];" : "=l"(x), "=l"(y) : "r"(a));
}

__global__ __launch_bounds__(NT, 1)
void natten7x7_kernel(const float* __restrict__ x,
                      const float* __restrict__ rpb,
                      float* __restrict__ out)
{
    extern __shared__ float smem[];
    float* ks = smem;                 // [14][2020]
    float* vs = smem + TELEMS;
    float* rs = smem + 2 * TELEMS;    // [169] rpb slice

    const int bh = blockIdx.y, b = bh >> 3, head = bh & 7;
    const int i0 = blockIdx.x * ROWS;
    const int r0 = min(max(i0 - 3, 0), HH - SROWS);

    const int j  = threadIdx.x;           // query col
    const int ty = threadIdx.y;           // query row 0..7
    const int tid = ty * WW + j;

    const float* xb = x + (size_t)b * (768 * PLANE);
    const float* kg = xb + (size_t)(256 + head * 32) * PLANE + r0 * WW;
    const float* vg = xb + (size_t)(512 + head * 32) * PLANE + r0 * WW;

    if (tid < 169) rs[tid] = rpb[head * 169 + tid];

    // ---- transpose-load K/V, division-free: thread owns slots tid and tid+448 ----
    {
        const int sr0 = tid / WW, c0 = tid - sr0 * WW;
        const int t1  = tid + NT;
        const int sr1 = t1 / WW,  c1 = t1 - sr1 * WW;
        const bool has1 = (t1 < SROWS * WW);
        #pragma unroll
        for (int tsel = 0; tsel < 2; tsel++) {
            const float* g = tsel ? vg : kg;
            float* sm = tsel ? vs : ks;
            #pragma unroll
            for (int dblk = 0; dblk < 8; dblk++) {
                const float* p0 = g + dblk * 4 * PLANE + tid;
                float4 v0 = make_float4(p0[0], p0[PLANE], p0[2 * PLANE], p0[3 * PLANE]);
                *(float4*)(sm + sr0 * RSTRIDE + c0 * CS + dblk * 4) = v0;
                if (has1) {
                    const float* p1 = g + dblk * 4 * PLANE + t1;
                    float4 v1 = make_float4(p1[0], p1[PLANE], p1[2 * PLANE], p1[3 * PLANE]);
                    *(float4*)(sm + sr1 * RSTRIDE + c1 * CS + dblk * 4) = v1;
                }
            }
        }
    }

    // ---- load + pack full-d q ----
    const int i = i0 + ty;
    const float scale = 0.17677669529663687f;  // 32^-0.5
    uint64_t q[16];
    {
        const float* qg = xb + (size_t)(head * 32) * PLANE + i * WW + j;
        #pragma unroll
        for (int t = 0; t < 16; t++)
            q[t] = pack2(qg[(2 * t) * PLANE] * scale, qg[(2 * t + 1) * PLANE] * scale);
    }
    __syncthreads();

    // ---- window geometry: this query's 7x7 window is always fully valid ----
    const int ni = min(max(i - 3, 0), HH - 7);
    const int nj = min(max(j - 3, 0), WW - 7);
    const int pi = 6 - (i - ni);
    const int pj = 6 - (j - nj);
    const int rbase = ni - r0;            // 0..7; rbase+6 <= 13 always

    const uint32_t sbase = (uint32_t)__cvta_generic_to_shared(ks)
                         + (uint32_t)(((rbase * RSTRIDE) + nj * CS) * 4);

    float s = 0.f;
    uint64_t o[16];
    #pragma unroll
    for (int t = 0; t < 16; t++) o[t] = 0ull;

    #pragma unroll
    for (int ki = 0; ki < 7; ki++) {
        const uint32_t rk = sbase + (uint32_t)(ki * (RSTRIDE * 4));
        const uint32_t rv = rk + (uint32_t)(TELEMS * 4);
        const float* biasrow = rs + (pi + ki) * 13 + pj;

        // -- 7 independent dots -> weights (no shuffles, no masks) --
        float w[7];
        #pragma unroll
        for (int kj = 0; kj < 7; kj++) {
            const uint32_t a = rk + (uint32_t)(kj * (CS * 4));
            uint64_t kt[8];
            #pragma unroll
            for (int u = 0; u < 4; u++) lds16(a + 16 * u, kt[2 * u], kt[2 * u + 1]);
            uint64_t a0 = ffma2(q[0], kt[0], 0ull), a1 = ffma2(q[1], kt[1], 0ull);
            #pragma unroll
            for (int t = 2; t < 8; t += 2) {
                a0 = ffma2(q[t], kt[t], a0);  a1 = ffma2(q[t + 1], kt[t + 1], a1);
            }
            #pragma unroll
            for (int u = 4; u < 8; u++) lds16(a + 16 * u, kt[2 * (u - 4)], kt[2 * (u - 4) + 1]);
            #pragma unroll
            for (int t = 0; t < 8; t += 2) {
                a0 = ffma2(q[8 + t], kt[t], a0);  a1 = ffma2(q[8 + t + 1], kt[t + 1], a1);
            }
            float2 f = unpack2(fadd2(a0, a1));
            w[kj] = __expf(f.x + f.y + biasrow[kj]);
        }
        #pragma unroll
        for (int kj = 0; kj < 7; kj++) s += w[kj];

        // -- 7 AV taps onto 16 independent accumulators --
        #pragma unroll
        for (int kj = 0; kj < 7; kj++) {
            const uint32_t a = rv + (uint32_t)(kj * (CS * 4));
            const uint64_t w2 = pack2(w[kj], w[kj]);
            uint64_t vt[8];
            #pragma unroll
            for (int u = 0; u < 4; u++) lds16(a + 16 * u, vt[2 * u], vt[2 * u + 1]);
            #pragma unroll
            for (int t = 0; t < 8; t++) o[t] = ffma2(w2, vt[t], o[t]);
            #pragma unroll
            for (int u = 4; u < 8; u++) lds16(a + 16 * u, vt[2 * (u - 4)], vt[2 * (u - 4) + 1]);
            #pragma unroll
            for (int t = 0; t < 8; t++) o[8 + t] = ffma2(w2, vt[t], o[8 + t]);
        }
    }

    const float inv = 1.0f / s;

    // ---- write out: full 32 dims of this query ----
    float* og = out + (size_t)b * (256 * PLANE)
              + (size_t)(head * 32) * PLANE + i * WW + j;
    #pragma unroll
    for (int t = 0; t < 16; t++) {
        float2 f = unpack2(o[t]);
        og[(2 * t) * PLANE]     = f.x * inv;
        og[(2 * t + 1) * PLANE] = f.y * inv;
    }
}

extern "C" void kernel_launch(void* const* d_in, const int* in_sizes, int n_in,
                              void* d_out, int out_size)
{
    const float* x   = (const float*)d_in[0];
    const float* rpb = (const float*)d_in[1];
    float* out = (float*)d_out;

    const int smem_bytes = (2 * TELEMS + 192) * sizeof(float);  // 227,008 B
    cudaFuncSetAttribute(natten7x7_kernel,
                         cudaFuncAttributeMaxDynamicSharedMemorySize, smem_bytes);

    dim3 grid(HH / ROWS, 2 * 8);   // 7 x 16 = 112 CTAs -> single wave
    dim3 block(WW, ROWS);          // 448 threads, one query each
    natten7x7_kernel<<<grid, block, smem_bytes>>>(x, rpb, out);
}

// round 10
// speedup vs baseline: 1.3346x; 1.3346x over previous
#include <cuda_runtime.h>
#include <cstdint>

// NATTEN 7x7, B=2, heads=8, d=32, 56x56, fp32.
// x: (B,768,56,56) qkv-packed; rpb: (8,13,13); out: (B,256,56,56).
// 224 threads/CTA, each owns 2 vertically-adjacent queries; 8-row stripe.
// Batch softmax without max-shift, log2-domain weights (single MUFU per tap).

#define HH 56
#define WW 56
#define PLANE 3136
#define ROWS 8
#define SROWS 14
#define NT 224
#define CS 36                     // padded d-stride per (row,col) slot
#define TSLOTS (SROWS * WW)       // 784
#define TELEMS (TSLOTS * CS)      // 28224 floats per tensor
#define LOG2E 1.4426950408889634f

__device__ __forceinline__ uint64_t pack2(float lo, float hi) {
    uint64_t r; asm("mov.b64 %0, {%1,%2};" : "=l"(r) : "f"(lo), "f"(hi)); return r;
}
__device__ __forceinline__ float2 unpack2(uint64_t v) {
    float2 f; asm("mov.b64 {%0,%1}, %2;" : "=f"(f.x), "=f"(f.y) : "l"(v)); return f;
}
__device__ __forceinline__ uint64_t ffma2(uint64_t a, uint64_t b, uint64_t c) {
    uint64_t d; asm("fma.rn.f32x2 %0, %1, %2, %3;" : "=l"(d) : "l"(a), "l"(b), "l"(c)); return d;
}
__device__ __forceinline__ uint64_t fadd2(uint64_t a, uint64_t b) {
    uint64_t d; asm("add.rn.f32x2 %0, %1, %2;" : "=l"(d) : "l"(a), "l"(b)); return d;
}
__device__ __forceinline__ void lds16(uint32_t a, uint64_t& x, uint64_t& y) {
    asm volatile("ld.shared.v2.b64 {%0,%1}, [%2];" : "=l"(x), "=l"(y) : "r"(a));
}
__device__ __forceinline__ float ex2(float x) {
    float y; asm("ex2.approx.f32 %0, %1;" : "=f"(y) : "f"(x)); return y;
}

__global__ __launch_bounds__(NT, 1)
void natten7x7_kernel(const float* __restrict__ x,
                      const float* __restrict__ rpb,
                      float* __restrict__ out)
{
    extern __shared__ float smem[];
    float* ks = smem;                 // [784][36]
    float* vs = smem + TELEMS;
    float* rs = smem + 2 * TELEMS;    // [192] rpb*log2e (pad covers guarded idx <= 181)

    const int bh = blockIdx.y, b = bh >> 3, head = bh & 7;
    const int i0 = blockIdx.x * ROWS;
    const int r0 = min(max(i0 - 3, 0), HH - SROWS);

    const int tx = threadIdx.x, ty = threadIdx.y;
    const int tid = ty * WW + tx;

    const float* xb = x + (size_t)b * (768 * PLANE);
    const float* kg = xb + (size_t)(256 + head * 32) * PLANE + r0 * WW;
    const float* vg = xb + (size_t)(512 + head * 32) * PLANE + r0 * WW;

    if (tid < 169) rs[tid] = rpb[head * 169 + tid] * LOG2E;

    // ---- transpose-load K/V, division-free: slot index is linear on both sides ----
    #pragma unroll
    for (int s = 0; s < 4; s++) {
        const int slot = tid + s * NT;            // rc = sr*56 + c, used directly
        if (s < 3 || slot < TSLOTS) {
            float* kd = ks + slot * CS;
            float* vd = vs + slot * CS;
            #pragma unroll
            for (int dblk = 0; dblk < 8; dblk++) {
                const float* pk = kg + dblk * 4 * PLANE + slot;
                const float* pv = vg + dblk * 4 * PLANE + slot;
                *(float4*)(kd + dblk * 4) = make_float4(pk[0], pk[PLANE], pk[2 * PLANE], pk[3 * PLANE]);
                *(float4*)(vd + dblk * 4) = make_float4(pv[0], pv[PLANE], pv[2 * PLANE], pv[3 * PLANE]);
            }
        }
    }

    // ---- load + pack q for both rows (scale includes log2e) ----
    const int iA = i0 + 2 * ty, iB = iA + 1, j = tx;
    const float scale = 0.17677669529663687f * LOG2E;
    uint64_t qA[16], qB[16];
    {
        const float* qa = xb + (size_t)(head * 32) * PLANE + iA * WW + j;
        const float* qb = qa + WW;
        #pragma unroll
        for (int t = 0; t < 16; t++) {
            qA[t] = pack2(qa[(2 * t) * PLANE] * scale, qa[(2 * t + 1) * PLANE] * scale);
            qB[t] = pack2(qb[(2 * t) * PLANE] * scale, qb[(2 * t + 1) * PLANE] * scale);
        }
    }
    __syncthreads();

    // ---- window geometry (union of two 7-row windows = 8 rows, off in {0,1}) ----
    const int niA = min(max(iA - 3, 0), HH - 7);
    const int niB = min(max(iB - 3, 0), HH - 7);
    const int off = niB - niA;
    const int piA = 6 - (iA - niA);
    const int piB = 6 - (iB - niB);
    const int nj  = min(max(j - 3, 0), WW - 7);
    const int pj  = 6 - (j - nj);
    const int rbase = niA - r0;   // 0..7 (7 only in edge stripes, where off==0)

    const uint32_t sbase = (uint32_t)__cvta_generic_to_shared(ks) + (uint32_t)(nj * CS * 4);

    // Clamped rows are always fully masked (rbase==7 implies off==0).
    int srow[8];
    #pragma unroll
    for (int rr = 0; rr < 8; rr++) srow[rr] = min(rbase + rr, SROWS - 1);

    // ---- pass 1: weights = ex2(dot + bias'), masked -> exactly 0 ----
    float pA[49], pB[56];
    float sA = 0.f, sB = 0.f;
    #pragma unroll
    for (int rr = 0; rr < 8; rr++) {
        const bool vB = off ? (rr >= 1) : (rr <= 6);
        #pragma unroll
        for (int kj = 0; kj < 7; kj++) {
            const uint32_t a = sbase + (uint32_t)((srow[rr] * WW + kj) * CS * 4);
            uint64_t kt[16];
            #pragma unroll
            for (int u = 0; u < 8; u++) lds16(a + 16 * u, kt[2 * u], kt[2 * u + 1]);

            if (rr < 7) {
                uint64_t a0 = ffma2(qA[0], kt[0], 0ull);
                uint64_t a1 = ffma2(qA[1], kt[1], 0ull);
                #pragma unroll
                for (int t = 2; t < 16; t += 2) {
                    a0 = ffma2(qA[t],     kt[t],     a0);
                    a1 = ffma2(qA[t + 1], kt[t + 1], a1);
                }
                float2 f = unpack2(fadd2(a0, a1));
                const float w = ex2(f.x + f.y + rs[(piA + rr) * 13 + pj + kj]);
                pA[rr * 7 + kj] = w;
                sA += w;
            }
            {
                uint64_t b0 = ffma2(qB[0], kt[0], 0ull);
                uint64_t b1 = ffma2(qB[1], kt[1], 0ull);
                #pragma unroll
                for (int t = 2; t < 16; t += 2) {
                    b0 = ffma2(qB[t],     kt[t],     b0);
                    b1 = ffma2(qB[t + 1], kt[t + 1], b1);
                }
                float2 f = unpack2(fadd2(b0, b1));
                const float bias = vB ? rs[(piB + rr - off) * 13 + pj + kj] : -1e30f;
                const float w = ex2(f.x + f.y + bias);
                pB[rr * 7 + kj] = w;
                sB += w;
            }
        }
    }
    const float invA = 1.0f / sA, invB = 1.0f / sB;

    // ---- pass 2: AV (shared V reads feed both queries) ----
    const uint32_t vbase = sbase + (uint32_t)(TELEMS * 4);
    uint64_t oA[16], oB[16];
    #pragma unroll
    for (int t = 0; t < 16; t++) { oA[t] = 0ull; oB[t] = 0ull; }
    #pragma unroll
    for (int rr = 0; rr < 8; rr++) {
        #pragma unroll
        for (int kj = 0; kj < 7; kj++) {
            const uint32_t a = vbase + (uint32_t)((srow[rr] * WW + kj) * CS * 4);
            uint64_t vt[16];
            #pragma unroll
            for (int u = 0; u < 8; u++) lds16(a + 16 * u, vt[2 * u], vt[2 * u + 1]);

            if (rr < 7) {
                const float w = pA[rr * 7 + kj];
                const uint64_t w2 = pack2(w, w);
                #pragma unroll
                for (int t = 0; t < 16; t++) oA[t] = ffma2(w2, vt[t], oA[t]);
            }
            {
                const float w = pB[rr * 7 + kj];   // masked entries are exactly 0
                const uint64_t w2 = pack2(w, w);
                #pragma unroll
                for (int t = 0; t < 16; t++) oB[t] = ffma2(w2, vt[t], oB[t]);
            }
        }
    }

    // ---- write out (B,256,56,56) ----
    float* oga = out + (size_t)b * (256 * PLANE) + (size_t)(head * 32) * PLANE + iA * WW + j;
    float* ogb = oga + WW;
    #pragma unroll
    for (int t = 0; t < 16; t++) {
        float2 fa = unpack2(oA[t]);
        float2 fb = unpack2(oB[t]);
        oga[(2 * t) * PLANE]     = fa.x * invA;
        oga[(2 * t + 1) * PLANE] = fa.y * invA;
        ogb[(2 * t) * PLANE]     = fb.x * invB;
        ogb[(2 * t + 1) * PLANE] = fb.y * invB;
    }
}

extern "C" void kernel_launch(void* const* d_in, const int* in_sizes, int n_in,
                              void* d_out, int out_size)
{
    const float* x   = (const float*)d_in[0];
    const float* rpb = (const float*)d_in[1];
    float* out = (float*)d_out;

    const int smem_bytes = (2 * TELEMS + 192) * sizeof(float);  // 226,560 B
    cudaFuncSetAttribute(natten7x7_kernel,
                         cudaFuncAttributeMaxDynamicSharedMemorySize, smem_bytes);

    dim3 grid(HH / ROWS, 2 * 8);   // 7 x 16 = 112 CTAs -> single wave
    dim3 block(WW, 4);             // 224 threads, each owns 2 query rows
    natten7x7_kernel<<<grid, block, smem_bytes>>>(x, rpb, out);
}